// round 4
// baseline (speedup 1.0000x reference)
#include <cuda_runtime.h>
#include <math.h>

#define Bsz  128
#define Tlen 1024
#define Hd   256
#define NOUT 2

typedef unsigned long long u64;

// Scratch buffers (device globals — allocation is forbidden)
__device__ float g_bufA[Bsz * Tlen * Hd];  // pre-activations
__device__ float g_bufB[Bsz * Tlen * Hd];  // layer-1 hidden states

// ---------- packed fp32x2 helpers (full-rate fp32 path on sm_103a) ----------
__device__ __forceinline__ void fma2(u64& acc, u64 a, u64 b) {
    asm("fma.rn.f32x2 %0, %1, %2, %0;" : "+l"(acc) : "l"(a), "l"(b));
}
__device__ __forceinline__ u64 add2(u64 a, u64 b) {
    u64 r; asm("add.rn.f32x2 %0, %1, %2;" : "=l"(r) : "l"(a), "l"(b)); return r;
}
__device__ __forceinline__ u64 dup2(float x) {
    u64 r; asm("mov.b64 %0, {%1, %1};" : "=l"(r) : "f"(x)); return r;
}
__device__ __forceinline__ float2 unpk(u64 v) {
    float2 r; asm("mov.b64 {%0, %1}, %2;" : "=f"(r.x), "=f"(r.y) : "l"(v)); return r;
}

// =============================================================================
// GEMM (unchanged — known good): out = A @ W^T + bias
// M=131072, N=K=256. Tile 128x128, 256 threads, K staged in 4 chunks of 64.
// =============================================================================
#define WS_STRIDE 130
#define AS_STRIDE 129
#define GEMM_SMEM ((Hd * WS_STRIDE + 64 * AS_STRIDE) * 4)

__global__ void __launch_bounds__(256, 1) gemm_kernel(
    const float* __restrict__ A, const float* __restrict__ W,
    const float* __restrict__ bias, float* __restrict__ out)
{
    extern __shared__ float sm[];
    float* Ws = sm;                    // [K=256][130]
    float* As = sm + Hd * WS_STRIDE;   // [64][129]

    const int t   = threadIdx.x;
    const int nt  = blockIdx.x & 1;
    const int mt  = blockIdx.x >> 1;
    const int m0  = mt * 128, n0 = nt * 128;
    const int kq  = t & 15;
    const int rn  = t >> 4;
    const int ml  = t & 15;
    const int tn2 = (t >> 4) << 1;

    const float4* W4 = (const float4*)(W + (size_t)n0 * Hd);
    #pragma unroll
    for (int p = 0; p < 8; ++p) {
        int row = rn + (p << 4);
        #pragma unroll
        for (int q = 0; q < 4; ++q) {
            float4 v = W4[row * 64 + (q << 4) + kq];
            int k = (((q << 4) + kq) << 2);
            Ws[(k + 0) * WS_STRIDE + row] = v.x;
            Ws[(k + 1) * WS_STRIDE + row] = v.y;
            Ws[(k + 2) * WS_STRIDE + row] = v.z;
            Ws[(k + 3) * WS_STRIDE + row] = v.w;
        }
    }

    u64 acc[8][4];
    #pragma unroll
    for (int i = 0; i < 8; ++i)
        #pragma unroll
        for (int j = 0; j < 4; ++j) acc[i][j] = 0ull;

    const float4* A4 = (const float4*)(A + (size_t)m0 * Hd);

    for (int s = 0; s < 4; ++s) {
        __syncthreads();
        #pragma unroll
        for (int p = 0; p < 8; ++p) {
            int row = rn + (p << 4);
            float4 v = A4[row * 64 + (s << 4) + kq];
            int k = kq << 2;
            As[(k + 0) * AS_STRIDE + row] = v.x;
            As[(k + 1) * AS_STRIDE + row] = v.y;
            As[(k + 2) * AS_STRIDE + row] = v.z;
            As[(k + 3) * AS_STRIDE + row] = v.w;
        }
        __syncthreads();

        const int kbase = s << 6;
        #pragma unroll 4
        for (int kk = 0; kk < 64; ++kk) {
            u64 ad[8];
            #pragma unroll
            for (int i = 0; i < 8; ++i)
                ad[i] = dup2(As[kk * AS_STRIDE + ml + (i << 4)]);
            u64 bp[4];
            #pragma unroll
            for (int j = 0; j < 4; ++j)
                bp[j] = *(const u64*)&Ws[(kbase + kk) * WS_STRIDE + tn2 + (j << 5)];
            #pragma unroll
            for (int i = 0; i < 8; ++i)
                #pragma unroll
                for (int j = 0; j < 4; ++j)
                    fma2(acc[i][j], ad[i], bp[j]);
        }
    }

    #pragma unroll
    for (int j = 0; j < 4; ++j) {
        int n = n0 + tn2 + (j << 5);
        float bv0 = bias[n], bv1 = bias[n + 1];
        #pragma unroll
        for (int i = 0; i < 8; ++i) {
            int m = m0 + ml + (i << 4);
            float2 v = unpk(acc[i][j]);
            float2 r; r.x = v.x + bv0; r.y = v.y + bv1;
            *(float2*)&out[(size_t)m * Hd + n] = r;
        }
    }
}

// =============================================================================
// Recurrence v3: 1 CTA = 1 batch row, 512 threads.
// Thread t -> output j = t>>1, K-half kh = t&1 (pair reduce via shfl_xor).
// ALL 128 weights/thread live in registers (32 float4 = 64 regs) -> zero
// smem weight traffic. Ping-pong h buffers -> one barrier per step.
// =============================================================================
#define RREG 32             // float4 (ulonglong2) in registers (128 floats)
#define HSTR 132            // padded half-stride (floats)
#define HBUF (2 * 2 * HSTR) // 2 parities x 2 halves
#define REC_SMEM (HBUF * 4)

__device__ __forceinline__ float fast_tanh(float x) {
    float e = __expf(2.0f * x);
    return 1.0f - 2.0f * __fdividef(1.0f, e + 1.0f);
}

template<bool WRITE_H, bool FINAL>
__global__ void __launch_bounds__(512, 1) recur_kernel(
    const float* __restrict__ pre, const float* __restrict__ Whh,
    float* __restrict__ hout,
    const float* __restrict__ fcw, const float* __restrict__ fcb,
    float* __restrict__ out)
{
    extern __shared__ float hbuf[];   // [2][2*HSTR]

    const int t  = threadIdx.x;
    const int b  = blockIdx.x;
    const int j  = t >> 1;
    const int kh = t & 1;

    // All 128 weights -> registers (32 ulonglong2)
    const ulonglong2* wg =
        (const ulonglong2*)(Whh + (size_t)j * Hd + (kh << 7));
    ulonglong2 wr[RREG];
    #pragma unroll
    for (int c = 0; c < RREG; ++c) wr[c] = wg[c];

    if (t < HBUF) hbuf[t] = 0.f;   // zero both parities (h0 = 0)

    const float* preb = pre + (size_t)b * Tlen * Hd;
    float p = preb[j];                        // pre for step 0
    const int wslot = j + ((j >> 7) << 2);    // padded write index
    __syncthreads();

    for (int step = 0; step < Tlen; ++step) {
        int sn = (step + 1 < Tlen) ? step + 1 : step;
        float pn = preb[sn * Hd + j];         // prefetch next pre

        const ulonglong2* h2 =
            (const ulonglong2*)(hbuf + (step & 1) * (2 * HSTR) + kh * HSTR);

        u64 ac[8];
        #pragma unroll
        for (int q = 0; q < 8; ++q) ac[q] = 0ull;

        #pragma unroll
        for (int c = 0; c < RREG; ++c) {
            ulonglong2 hv = h2[c];
            fma2(ac[((c & 3) << 1) + 0], wr[c].x, hv.x);
            fma2(ac[((c & 3) << 1) + 1], wr[c].y, hv.y);
        }

        u64 s01 = add2(add2(add2(ac[0], ac[1]), add2(ac[2], ac[3])),
                       add2(add2(ac[4], ac[5]), add2(ac[6], ac[7])));
        float2 f = unpk(s01);
        float d = f.x + f.y;
        d += __shfl_xor_sync(0xffffffffu, d, 1);   // fold K-halves

        float hn = fast_tanh(p + d);

        if (kh == 0) {
            hbuf[((step + 1) & 1) * (2 * HSTR) + wslot] = hn;
            if (WRITE_H)
                hout[((size_t)b * Tlen + step) * Hd + j] = hn;
        }
        __syncthreads();
        p = pn;
    }

    if (FINAL) {
        if (t < 64) {
            int o = t >> 5, lane = t & 31;
            float s = 0.f;
            #pragma unroll
            for (int q = 0; q < 8; ++q) {
                int jj = lane + (q << 5);
                s += hbuf[jj + ((jj >> 7) << 2)] * fcw[o * Hd + jj];
            }
            #pragma unroll
            for (int off = 16; off; off >>= 1)
                s += __shfl_down_sync(0xffffffffu, s, off);
            if (lane == 0) out[b * NOUT + o] = s + fcb[o];
        }
    }
}

extern "C" void kernel_launch(void* const* d_in, const int* in_sizes, int n_in,
                              void* d_out, int out_size) {
    const float* x    = (const float*)d_in[0];
    const float* Wxh0 = (const float*)d_in[1];
    const float* Whh0 = (const float*)d_in[2];
    const float* b0   = (const float*)d_in[3];
    const float* Wxh1 = (const float*)d_in[4];
    const float* Whh1 = (const float*)d_in[5];
    const float* b1   = (const float*)d_in[6];
    const float* fcw  = (const float*)d_in[7];
    const float* fcb  = (const float*)d_in[8];
    float* out = (float*)d_out;

    float *bufA = nullptr, *bufB = nullptr;
    cudaGetSymbolAddress((void**)&bufA, g_bufA);
    cudaGetSymbolAddress((void**)&bufB, g_bufB);

    cudaFuncSetAttribute(gemm_kernel,
        cudaFuncAttributeMaxDynamicSharedMemorySize, GEMM_SMEM);

    // Layer 1
    gemm_kernel<<<2048, 256, GEMM_SMEM>>>(x, Wxh0, b0, bufA);
    recur_kernel<true, false><<<Bsz, 512, REC_SMEM>>>(
        bufA, Whh0, bufB, nullptr, nullptr, nullptr);

    // Layer 2 + head
    gemm_kernel<<<2048, 256, GEMM_SMEM>>>(bufB, Wxh1, b1, bufA);
    recur_kernel<false, true><<<Bsz, 512, REC_SMEM>>>(
        bufA, Whh1, nullptr, fcw, fcb, out);
}

// round 5
// speedup vs baseline: 1.2975x; 1.2975x over previous
#include <cuda_runtime.h>
#include <math.h>

#define Bsz  128
#define Tlen 1024
#define Hd   256
#define NOUT 2

typedef unsigned long long u64;

// Scratch buffers (device globals — allocation is forbidden)
__device__ float g_bufA[Bsz * Tlen * Hd];  // pre-activations
__device__ float g_bufB[Bsz * Tlen * Hd];  // layer-1 hidden states

// ---------- packed fp32x2 helpers (full-rate fp32 path on sm_103a) ----------
__device__ __forceinline__ void fma2(u64& acc, u64 a, u64 b) {
    asm("fma.rn.f32x2 %0, %1, %2, %0;" : "+l"(acc) : "l"(a), "l"(b));
}
__device__ __forceinline__ u64 add2(u64 a, u64 b) {
    u64 r; asm("add.rn.f32x2 %0, %1, %2;" : "=l"(r) : "l"(a), "l"(b)); return r;
}
__device__ __forceinline__ u64 dup2(float x) {
    u64 r; asm("mov.b64 %0, {%1, %1};" : "=l"(r) : "f"(x)); return r;
}
__device__ __forceinline__ float2 unpk(u64 v) {
    float2 r; asm("mov.b64 {%0, %1}, %2;" : "=f"(r.x), "=f"(r.y) : "l"(v)); return r;
}

// =============================================================================
// GEMM: out = A @ W^T + bias;  M=131072, N=K=256.
// Tile 128x128, 256 threads, K staged in 4 chunks of 64.
// v2: next A chunk prefetched into registers BEFORE the compute barrier so
// LDG latency hides under the previous chunk's FMA work.
// =============================================================================
#define WS_STRIDE 130
#define AS_STRIDE 129
#define GEMM_SMEM ((Hd * WS_STRIDE + 64 * AS_STRIDE) * 4)

__global__ void __launch_bounds__(256, 1) gemm_kernel(
    const float* __restrict__ A, const float* __restrict__ W,
    const float* __restrict__ bias, float* __restrict__ out)
{
    extern __shared__ float sm[];
    float* Ws = sm;                    // [K=256][130]
    float* As = sm + Hd * WS_STRIDE;   // [64][129]

    const int t   = threadIdx.x;
    const int nt  = blockIdx.x & 1;
    const int mt  = blockIdx.x >> 1;
    const int m0  = mt * 128, n0 = nt * 128;
    const int kq  = t & 15;
    const int rn  = t >> 4;
    const int ml  = t & 15;
    const int tn2 = (t >> 4) << 1;

    const float4* W4 = (const float4*)(W + (size_t)n0 * Hd);
    #pragma unroll
    for (int p = 0; p < 8; ++p) {
        int row = rn + (p << 4);
        #pragma unroll
        for (int q = 0; q < 4; ++q) {
            float4 v = W4[row * 64 + (q << 4) + kq];
            int k = (((q << 4) + kq) << 2);
            Ws[(k + 0) * WS_STRIDE + row] = v.x;
            Ws[(k + 1) * WS_STRIDE + row] = v.y;
            Ws[(k + 2) * WS_STRIDE + row] = v.z;
            Ws[(k + 3) * WS_STRIDE + row] = v.w;
        }
    }

    u64 acc[8][4];
    #pragma unroll
    for (int i = 0; i < 8; ++i)
        #pragma unroll
        for (int j = 0; j < 4; ++j) acc[i][j] = 0ull;

    const float4* A4 = (const float4*)(A + (size_t)m0 * Hd);

    // prefetch chunk 0 into registers
    float4 v[8];
    #pragma unroll
    for (int p = 0; p < 8; ++p)
        v[p] = A4[(rn + (p << 4)) * 64 + kq];

    for (int s = 0; s < 4; ++s) {
        __syncthreads();  // previous chunk's compute done reading As
        #pragma unroll
        for (int p = 0; p < 8; ++p) {
            int row = rn + (p << 4);
            int k = kq << 2;
            As[(k + 0) * AS_STRIDE + row] = v[p].x;
            As[(k + 1) * AS_STRIDE + row] = v[p].y;
            As[(k + 2) * AS_STRIDE + row] = v[p].z;
            As[(k + 3) * AS_STRIDE + row] = v[p].w;
        }
        if (s < 3) {
            #pragma unroll
            for (int p = 0; p < 8; ++p)
                v[p] = A4[(rn + (p << 4)) * 64 + ((s + 1) << 4) + kq];
        }
        __syncthreads();

        const int kbase = s << 6;
        #pragma unroll 4
        for (int kk = 0; kk < 64; ++kk) {
            u64 ad[8];
            #pragma unroll
            for (int i = 0; i < 8; ++i)
                ad[i] = dup2(As[kk * AS_STRIDE + ml + (i << 4)]);
            u64 bp[4];
            #pragma unroll
            for (int j = 0; j < 4; ++j)
                bp[j] = *(const u64*)&Ws[(kbase + kk) * WS_STRIDE + tn2 + (j << 5)];
            #pragma unroll
            for (int i = 0; i < 8; ++i)
                #pragma unroll
                for (int j = 0; j < 4; ++j)
                    fma2(acc[i][j], ad[i], bp[j]);
        }
    }

    #pragma unroll
    for (int j = 0; j < 4; ++j) {
        int n = n0 + tn2 + (j << 5);
        float bv0 = bias[n], bv1 = bias[n + 1];
        #pragma unroll
        for (int i = 0; i < 8; ++i) {
            int m = m0 + ml + (i << 4);
            float2 vv = unpk(acc[i][j]);
            float2 r; r.x = vv.x + bv0; r.y = vv.y + bv1;
            *(float2*)&out[(size_t)m * Hd + n] = r;
        }
    }
}

// =============================================================================
// Recurrence (R2 structure — best known): 1 CTA = 1 batch row, 512 threads.
// Thread t -> output j = t>>1, K-half kh = t&1 (pair reduce via shfl_xor).
// Weights/thread = 128 floats: 80 in registers + 48 in smem (no-spill split).
// Ping-pong h buffers -> one barrier per step. 6 accumulators (chain depth
// 10/10/12 instead of 20/20/12).
// =============================================================================
#define RREG 20   // float4 in registers (80 floats)
#define RSM  12   // float4 in smem (48 floats)
#define HSTR 132            // padded half-stride (floats)
#define HBUF (2 * 2 * HSTR)
#define REC_SMEM (HBUF * 4 + RSM * 512 * 16)

__device__ __forceinline__ float fast_tanh(float x) {
    float e = __expf(2.0f * x);
    return 1.0f - 2.0f * __fdividef(1.0f, e + 1.0f);
}

template<bool WRITE_H, bool FINAL>
__global__ void __launch_bounds__(512, 1) recur_kernel(
    const float* __restrict__ pre, const float* __restrict__ Whh,
    float* __restrict__ hout,
    const float* __restrict__ fcw, const float* __restrict__ fcb,
    float* __restrict__ out)
{
    extern __shared__ float smf[];
    float* hbuf = smf;                                   // [2][2*HSTR]
    ulonglong2* Wsm = (ulonglong2*)(smf + HBUF);         // [RSM][512]

    const int t  = threadIdx.x;
    const int b  = blockIdx.x;
    const int j  = t >> 1;
    const int kh = t & 1;

    const ulonglong2* wg =
        (const ulonglong2*)(Whh + (size_t)j * Hd + (kh << 7));
    ulonglong2 wr[RREG];
    #pragma unroll
    for (int c = 0; c < RREG; ++c) wr[c] = wg[c];
    #pragma unroll
    for (int c = 0; c < RSM; ++c) Wsm[c * 512 + t] = wg[RREG + c];

    if (t < HBUF) hbuf[t] = 0.f;

    const float* preb = pre + (size_t)b * Tlen * Hd;
    float p = preb[j];
    const int wslot = j + ((j >> 7) << 2);
    __syncthreads();

    for (int step = 0; step < Tlen; ++step) {
        int sn = (step + 1 < Tlen) ? step + 1 : step;
        float pn = preb[sn * Hd + j];

        const ulonglong2* h2 =
            (const ulonglong2*)(hbuf + (step & 1) * (2 * HSTR) + kh * HSTR);

        u64 a0 = 0ull, a1 = 0ull, a2 = 0ull, a3 = 0ull, a4 = 0ull, a5 = 0ull;

        // smem-resident weights first: fills the LSU pipe early
        #pragma unroll
        for (int c = 0; c < RSM; ++c) {
            ulonglong2 hv = h2[RREG + c];
            ulonglong2 wv = Wsm[c * 512 + t];
            fma2(a4, wv.x, hv.x);
            fma2(a5, wv.y, hv.y);
        }
        #pragma unroll
        for (int c = 0; c < RREG; c += 2) {
            ulonglong2 hv = h2[c];
            fma2(a0, wr[c].x, hv.x);
            fma2(a1, wr[c].y, hv.y);
            ulonglong2 hw = h2[c + 1];
            fma2(a2, wr[c + 1].x, hw.x);
            fma2(a3, wr[c + 1].y, hw.y);
        }

        u64 s01 = add2(add2(add2(a0, a1), add2(a2, a3)), add2(a4, a5));
        float2 f = unpk(s01);
        float d = f.x + f.y;
        d += __shfl_xor_sync(0xffffffffu, d, 1);

        float hn = fast_tanh(p + d);

        if (kh == 0) {
            hbuf[((step + 1) & 1) * (2 * HSTR) + wslot] = hn;
            if (WRITE_H)
                hout[((size_t)b * Tlen + step) * Hd + j] = hn;
        }
        __syncthreads();
        p = pn;
    }

    if (FINAL) {
        if (t < 64) {
            int o = t >> 5, lane = t & 31;
            float s = 0.f;
            #pragma unroll
            for (int q = 0; q < 8; ++q) {
                int jj = lane + (q << 5);
                s += hbuf[jj + ((jj >> 7) << 2)] * fcw[o * Hd + jj];
            }
            #pragma unroll
            for (int off = 16; off; off >>= 1)
                s += __shfl_down_sync(0xffffffffu, s, off);
            if (lane == 0) out[b * NOUT + o] = s + fcb[o];
        }
    }
}

extern "C" void kernel_launch(void* const* d_in, const int* in_sizes, int n_in,
                              void* d_out, int out_size) {
    const float* x    = (const float*)d_in[0];
    const float* Wxh0 = (const float*)d_in[1];
    const float* Whh0 = (const float*)d_in[2];
    const float* b0   = (const float*)d_in[3];
    const float* Wxh1 = (const float*)d_in[4];
    const float* Whh1 = (const float*)d_in[5];
    const float* b1   = (const float*)d_in[6];
    const float* fcw  = (const float*)d_in[7];
    const float* fcb  = (const float*)d_in[8];
    float* out = (float*)d_out;

    float *bufA = nullptr, *bufB = nullptr;
    cudaGetSymbolAddress((void**)&bufA, g_bufA);
    cudaGetSymbolAddress((void**)&bufB, g_bufB);

    cudaFuncSetAttribute(gemm_kernel,
        cudaFuncAttributeMaxDynamicSharedMemorySize, GEMM_SMEM);
    cudaFuncSetAttribute(recur_kernel<true, false>,
        cudaFuncAttributeMaxDynamicSharedMemorySize, REC_SMEM);
    cudaFuncSetAttribute(recur_kernel<false, true>,
        cudaFuncAttributeMaxDynamicSharedMemorySize, REC_SMEM);

    // Layer 1
    gemm_kernel<<<2048, 256, GEMM_SMEM>>>(x, Wxh0, b0, bufA);
    recur_kernel<true, false><<<Bsz, 512, REC_SMEM>>>(
        bufA, Whh0, bufB, nullptr, nullptr, nullptr);

    // Layer 2 + head
    gemm_kernel<<<2048, 256, GEMM_SMEM>>>(bufB, Wxh1, b1, bufA);
    recur_kernel<false, true><<<Bsz, 512, REC_SMEM>>>(
        bufA, Whh1, nullptr, fcw, fcb, out);
}

// round 6
// speedup vs baseline: 1.3234x; 1.0200x over previous
#include <cuda_runtime.h>
#include <math.h>

#define Bsz  128
#define Tlen 1024
#define Hd   256
#define NOUT 2

typedef unsigned long long u64;

// Scratch buffers (device globals — allocation is forbidden)
__device__ float g_bufA[Bsz * Tlen * Hd];  // pre-activations
__device__ float g_bufB[Bsz * Tlen * Hd];  // layer-1 hidden states

// ---------- packed fp32x2 helpers (full-rate fp32 path on sm_103a) ----------
__device__ __forceinline__ void fma2(u64& acc, u64 a, u64 b) {
    asm("fma.rn.f32x2 %0, %1, %2, %0;" : "+l"(acc) : "l"(a), "l"(b));
}
__device__ __forceinline__ u64 add2(u64 a, u64 b) {
    u64 r; asm("add.rn.f32x2 %0, %1, %2;" : "=l"(r) : "l"(a), "l"(b)); return r;
}
__device__ __forceinline__ float2 unpk(u64 v) {
    float2 r; asm("mov.b64 {%0, %1}, %2;" : "=f"(r.x), "=f"(r.y) : "l"(v)); return r;
}

// =============================================================================
// GEMM: out = A @ W^T + bias;  M=131072, N=K=256.
// Tile 128x128, 256 threads, K staged in 4 chunks of 64.
// A staged DUPLICATED (each value stored twice) so the m-operand of the
// packed FMA loads as a single LDS.64 -> no MOV-duplication in the kk body.
// =============================================================================
#define WS_STRIDE 130
#define AS_STRIDE 258   // 128 m-values x 2 (duplicated) + 2 pad; even for 8B align
#define GEMM_SMEM ((Hd * WS_STRIDE + 64 * AS_STRIDE) * 4)

__global__ void __launch_bounds__(256, 1) gemm_kernel(
    const float* __restrict__ A, const float* __restrict__ W,
    const float* __restrict__ bias, float* __restrict__ out)
{
    extern __shared__ float sm[];
    float* Ws = sm;                    // [K=256][130]   (k-major, n contiguous)
    float* As = sm + Hd * WS_STRIDE;   // [64][258]      (k-major, m duplicated)

    const int t   = threadIdx.x;
    const int nt  = blockIdx.x & 1;
    const int mt  = blockIdx.x >> 1;
    const int m0  = mt * 128, n0 = nt * 128;
    const int kq  = t & 15;
    const int rn  = t >> 4;
    const int ml  = t & 15;
    const int tn2 = (t >> 4) << 1;

    const float4* W4 = (const float4*)(W + (size_t)n0 * Hd);
    #pragma unroll
    for (int p = 0; p < 8; ++p) {
        int row = rn + (p << 4);
        #pragma unroll
        for (int q = 0; q < 4; ++q) {
            float4 v = W4[row * 64 + (q << 4) + kq];
            int k = (((q << 4) + kq) << 2);
            Ws[(k + 0) * WS_STRIDE + row] = v.x;
            Ws[(k + 1) * WS_STRIDE + row] = v.y;
            Ws[(k + 2) * WS_STRIDE + row] = v.z;
            Ws[(k + 3) * WS_STRIDE + row] = v.w;
        }
    }

    u64 acc[8][4];
    #pragma unroll
    for (int i = 0; i < 8; ++i)
        #pragma unroll
        for (int j = 0; j < 4; ++j) acc[i][j] = 0ull;

    const float4* A4 = (const float4*)(A + (size_t)m0 * Hd);

    // prefetch chunk 0
    float4 v[8];
    #pragma unroll
    for (int p = 0; p < 8; ++p)
        v[p] = A4[(rn + (p << 4)) * 64 + kq];

    for (int s = 0; s < 4; ++s) {
        __syncthreads();
        #pragma unroll
        for (int p = 0; p < 8; ++p) {
            int row2 = (rn + (p << 4)) << 1;
            int k0 = kq << 2;
            *(float2*)&As[(k0 + 0) * AS_STRIDE + row2] = make_float2(v[p].x, v[p].x);
            *(float2*)&As[(k0 + 1) * AS_STRIDE + row2] = make_float2(v[p].y, v[p].y);
            *(float2*)&As[(k0 + 2) * AS_STRIDE + row2] = make_float2(v[p].z, v[p].z);
            *(float2*)&As[(k0 + 3) * AS_STRIDE + row2] = make_float2(v[p].w, v[p].w);
        }
        if (s < 3) {
            #pragma unroll
            for (int p = 0; p < 8; ++p)
                v[p] = A4[(rn + (p << 4)) * 64 + ((s + 1) << 4) + kq];
        }
        __syncthreads();

        const int kbase = s << 6;
        #pragma unroll 4
        for (int kk = 0; kk < 64; ++kk) {
            u64 ad[8];
            #pragma unroll
            for (int i = 0; i < 8; ++i)
                ad[i] = *(const u64*)&As[kk * AS_STRIDE + ((ml + (i << 4)) << 1)];
            u64 bp[4];
            #pragma unroll
            for (int j = 0; j < 4; ++j)
                bp[j] = *(const u64*)&Ws[(kbase + kk) * WS_STRIDE + tn2 + (j << 5)];
            #pragma unroll
            for (int i = 0; i < 8; ++i)
                #pragma unroll
                for (int j = 0; j < 4; ++j)
                    fma2(acc[i][j], ad[i], bp[j]);
        }
    }

    #pragma unroll
    for (int j = 0; j < 4; ++j) {
        int n = n0 + tn2 + (j << 5);
        float bv0 = bias[n], bv1 = bias[n + 1];
        #pragma unroll
        for (int i = 0; i < 8; ++i) {
            int m = m0 + ml + (i << 4);
            float2 vv = unpk(acc[i][j]);
            float2 r; r.x = vv.x + bv0; r.y = vv.y + bv1;
            *(float2*)&out[(size_t)m * Hd + n] = r;
        }
    }
}

// =============================================================================
// Recurrence v4: 1 CTA = 1 batch row, 512 threads.
// Thread t -> output j = t>>1, K-half kh = t&1 (pair reduce via shfl_xor).
// Weights: 80 floats in regs + 48 in smem (no-spill split).
// h ping-pong buffer INTERLEAVED at 16B-chunk granularity:
//   h[kh*128 + 4c + i]  lives at  float offset  c*8 + kh*4 + i
// so each warp's LDS.128 touches one 32B span -> 1 L1 wavefront (was 2).
// =============================================================================
#define RREG 20   // float4 in registers (80 floats)
#define RSM  12   // float4 in smem (48 floats)
#define HBUF 512  // 2 parities x 256 floats
#define REC_SMEM (HBUF * 4 + RSM * 512 * 16)

__device__ __forceinline__ float fast_tanh(float x) {
    float e = __expf(2.0f * x);
    return 1.0f - 2.0f * __fdividef(1.0f, e + 1.0f);
}

// permuted slot of h[j] inside one 256-float parity block
__device__ __forceinline__ int hslot(int j) {
    return ((j & 127) >> 2) * 8 + ((j >> 7) << 2) + (j & 3);
}

template<bool WRITE_H, bool FINAL>
__global__ void __launch_bounds__(512, 1) recur_kernel(
    const float* __restrict__ pre, const float* __restrict__ Whh,
    float* __restrict__ hout,
    const float* __restrict__ fcw, const float* __restrict__ fcb,
    float* __restrict__ out)
{
    extern __shared__ float smf[];
    float* hbuf = smf;                                   // [2][256] interleaved
    ulonglong2* Wsm = (ulonglong2*)(smf + HBUF);         // [RSM][512]

    const int t  = threadIdx.x;
    const int b  = blockIdx.x;
    const int j  = t >> 1;
    const int kh = t & 1;

    const ulonglong2* wg =
        (const ulonglong2*)(Whh + (size_t)j * Hd + (kh << 7));
    ulonglong2 wr[RREG];
    #pragma unroll
    for (int c = 0; c < RREG; ++c) wr[c] = wg[c];
    #pragma unroll
    for (int c = 0; c < RSM; ++c) Wsm[c * 512 + t] = wg[RREG + c];

    if (t < HBUF) hbuf[t] = 0.f;   // zero both parities (h0 = 0)

    const float* preb = pre + (size_t)b * Tlen * Hd;
    float p = preb[j];
    const int wslot = hslot(j);
    __syncthreads();

    for (int step = 0; step < Tlen; ++step) {
        int sn = (step + 1 < Tlen) ? step + 1 : step;
        float pn = preb[sn * Hd + j];

        // chunk (kh, c) of current h lives at 16B index  c*2 + kh
        const ulonglong2* hb =
            (const ulonglong2*)(hbuf + (step & 1) * 256) + kh;

        u64 a0 = 0ull, a1 = 0ull, a2 = 0ull, a3 = 0ull, a4 = 0ull, a5 = 0ull;

        // smem-resident weights first (chunks RREG..RREG+RSM-1)
        #pragma unroll
        for (int c = 0; c < RSM; ++c) {
            ulonglong2 hv = hb[(RREG + c) << 1];
            ulonglong2 wv = Wsm[c * 512 + t];
            fma2(a4, wv.x, hv.x);
            fma2(a5, wv.y, hv.y);
        }
        #pragma unroll
        for (int c = 0; c < RREG; c += 2) {
            ulonglong2 hv = hb[c << 1];
            fma2(a0, wr[c].x, hv.x);
            fma2(a1, wr[c].y, hv.y);
            ulonglong2 hw = hb[(c + 1) << 1];
            fma2(a2, wr[c + 1].x, hw.x);
            fma2(a3, wr[c + 1].y, hw.y);
        }

        u64 s01 = add2(add2(add2(a0, a1), add2(a2, a3)), add2(a4, a5));
        float2 f = unpk(s01);
        float d = f.x + f.y;
        d += __shfl_xor_sync(0xffffffffu, d, 1);   // fold K-halves

        float hn = fast_tanh(p + d);

        if (kh == 0) {
            hbuf[((step + 1) & 1) * 256 + wslot] = hn;
            if (WRITE_H)
                hout[((size_t)b * Tlen + step) * Hd + j] = hn;
        }
        __syncthreads();
        p = pn;
    }

    if (FINAL) {
        // final h is in parity (Tlen & 1) == 0, permuted layout
        if (t < 64) {
            int o = t >> 5, lane = t & 31;
            float s = 0.f;
            #pragma unroll
            for (int q = 0; q < 8; ++q) {
                int jj = lane + (q << 5);
                s += hbuf[hslot(jj)] * fcw[o * Hd + jj];
            }
            #pragma unroll
            for (int off = 16; off; off >>= 1)
                s += __shfl_down_sync(0xffffffffu, s, off);
            if (lane == 0) out[b * NOUT + o] = s + fcb[o];
        }
    }
}

extern "C" void kernel_launch(void* const* d_in, const int* in_sizes, int n_in,
                              void* d_out, int out_size) {
    const float* x    = (const float*)d_in[0];
    const float* Wxh0 = (const float*)d_in[1];
    const float* Whh0 = (const float*)d_in[2];
    const float* b0   = (const float*)d_in[3];
    const float* Wxh1 = (const float*)d_in[4];
    const float* Whh1 = (const float*)d_in[5];
    const float* b1   = (const float*)d_in[6];
    const float* fcw  = (const float*)d_in[7];
    const float* fcb  = (const float*)d_in[8];
    float* out = (float*)d_out;

    float *bufA = nullptr, *bufB = nullptr;
    cudaGetSymbolAddress((void**)&bufA, g_bufA);
    cudaGetSymbolAddress((void**)&bufB, g_bufB);

    cudaFuncSetAttribute(gemm_kernel,
        cudaFuncAttributeMaxDynamicSharedMemorySize, GEMM_SMEM);
    cudaFuncSetAttribute(recur_kernel<true, false>,
        cudaFuncAttributeMaxDynamicSharedMemorySize, REC_SMEM);
    cudaFuncSetAttribute(recur_kernel<false, true>,
        cudaFuncAttributeMaxDynamicSharedMemorySize, REC_SMEM);

    // Layer 1
    gemm_kernel<<<2048, 256, GEMM_SMEM>>>(x, Wxh0, b0, bufA);
    recur_kernel<true, false><<<Bsz, 512, REC_SMEM>>>(
        bufA, Whh0, bufB, nullptr, nullptr, nullptr);

    // Layer 2 + head
    gemm_kernel<<<2048, 256, GEMM_SMEM>>>(bufB, Wxh1, b1, bufA);
    recur_kernel<false, true><<<Bsz, 512, REC_SMEM>>>(
        bufA, Whh1, nullptr, fcw, fcb, out);
}